// round 11
// baseline (speedup 1.0000x reference)
#include <cuda_runtime.h>
#include <math.h>

#define BATCH 32
#define A_AP 0.85f
#define A_DS 0.1f
#define CC1 (0.01f * 0.01f)
#define CC2 (0.03f * 0.03f)
#define NT 512

// ---- static device scratch (no allocs allowed) ----
#define OFF_L1 0
#define OFF_L2 3145728
#define OFF_L3 3932160
#define PYR_TOT 4128768
__device__ float g_pyr_l[PYR_TOT];
__device__ float g_pyr_r[PYR_TOT];
// accumulators: AP, LR, DS
__device__ double g_acc[3];

// -------------------- helpers --------------------
__device__ __forceinline__ float blockReduce(float v) {
    __shared__ float sh[32];
    int tid = threadIdx.x;
    int lane = tid & 31;
    int wid = tid >> 5;
    #pragma unroll
    for (int o = 16; o; o >>= 1) v += __shfl_down_sync(0xffffffffu, v, o);
    if (lane == 0) sh[wid] = v;
    __syncthreads();
    int nw = blockDim.x >> 5;
    v = (tid < nw) ? sh[tid] : 0.0f;
    if (wid == 0) {
        #pragma unroll
        for (int o = 16; o; o >>= 1) v += __shfl_down_sync(0xffffffffu, v, o);
    }
    return v;
}

// reduce two values with a single barrier round
__device__ __forceinline__ float2 blockReduce2(float a, float b) {
    __shared__ float sha[32], shb[32];
    int tid = threadIdx.x;
    int lane = tid & 31;
    int wid = tid >> 5;
    #pragma unroll
    for (int o = 16; o; o >>= 1) {
        a += __shfl_down_sync(0xffffffffu, a, o);
        b += __shfl_down_sync(0xffffffffu, b, o);
    }
    if (lane == 0) { sha[wid] = a; shb[wid] = b; }
    __syncthreads();
    int nw = blockDim.x >> 5;
    a = (tid < nw) ? sha[tid] : 0.0f;
    b = (tid < nw) ? shb[tid] : 0.0f;
    if (wid == 0) {
        #pragma unroll
        for (int o = 16; o; o >>= 1) {
            a += __shfl_down_sync(0xffffffffu, a, o);
            b += __shfl_down_sync(0xffffffffu, b, o);
        }
    }
    return make_float2(a, b);
}

__global__ void zero_acc_kernel() {
    if (threadIdx.x < 3) g_acc[threadIdx.x] = 0.0;
}

// bilinear align_corners resize, both sides in one launch
__global__ void resize_kernel(const float* __restrict__ inL, const float* __restrict__ inR,
                              float* __restrict__ outL, float* __restrict__ outR,
                              int Hin, int Win, int Hout, int Wout) {
    int idx = blockIdx.x * blockDim.x + threadIdx.x;
    int total = 2 * BATCH * 3 * Hout * Wout;
    if (idx >= total) return;
    int i = idx % Wout; int t = idx / Wout;
    int j = t % Hout;   t /= Hout;
    int c = t % 3;      int b2 = t / 3;
    int side = (b2 >= BATCH);
    int b = b2 - side * BATCH;
    const float* in = side ? inR : inL;
    float* out = side ? outR : outL;

    float sy = (float)(Hin - 1) / (float)(Hout - 1);
    float sx = (float)(Win - 1) / (float)(Wout - 1);
    float y = j * sy, x = i * sx;
    int y0 = (int)floorf(y);
    int y1 = min(y0 + 1, Hin - 1);
    int x0 = (int)floorf(x);
    int x1 = min(x0 + 1, Win - 1);
    float wy = y - (float)y0;
    float wx = x - (float)x0;
    const float* p = in + ((long)(b * 3 + c) * Hin) * Win;
    float tl = p[y0 * Win + x0], tr = p[y0 * Win + x1];
    float bl = p[y1 * Win + x0], br = p[y1 * Win + x1];
    float top = tl * (1.f - wy) + bl * wy;
    float bot = tr * (1.f - wy) + br * wy;
    out[((long)(b * 3 + c) * Hout + j) * Wout + i] = top * (1.f - wx) + bot * wx;
}

// 1-D bilinear gather from a shared row, zero padding outside [0,W-1]
__device__ __forceinline__ float sample_sh(const float* __restrict__ row, float x, int W) {
    float x0f = floorf(x);
    int x0 = (int)x0f;
    float w1 = x - x0f;
    float v = 0.f;
    if (x0 >= 0 && x0 < W) v += row[x0] * (1.f - w1);
    int x1 = x0 + 1;
    if (x1 >= 0 && x1 < W) v += row[x1] * w1;
    return v;
}

// horizontal 3-sums for both stereo sides at shared index 'base'
__device__ __forceinline__ void hsum10(const float* __restrict__ Xl, const float* __restrict__ El,
                                       const float* __restrict__ Xr, const float* __restrict__ Er,
                                       int base, float* o) {
    float x0 = Xl[base - 1], x1 = Xl[base], x2 = Xl[base + 1];
    float e0 = El[base - 1], e1 = El[base], e2 = El[base + 1];
    o[0] = x0 + x1 + x2;
    o[1] = e0 + e1 + e2;
    o[2] = x0 * x0 + x1 * x1 + x2 * x2;
    o[3] = e0 * e0 + e1 * e1 + e2 * e2;
    o[4] = x0 * e0 + x1 * e1 + x2 * e2;
    float u0 = Xr[base - 1], u1 = Xr[base], u2 = Xr[base + 1];
    float v0 = Er[base - 1], v1 = Er[base], v2 = Er[base + 1];
    o[5] = u0 + u1 + u2;
    o[6] = v0 + v1 + v2;
    o[7] = u0 * u0 + u1 * u1 + u2 * u2;
    o[8] = v0 * v0 + v1 * v1 + v2 * v2;
    o[9] = u0 * v0 + u1 * v1 + u2 * v2;
}

__device__ __forceinline__ float ssim_val(float sx, float sy, float sxx, float syy, float sxy) {
    const float inv9 = 1.f / 9.f;
    float mux = sx * inv9, muy = sy * inv9;
    float sigx = sxx * inv9 - mux * mux;
    float sigy = syy * inv9 - muy * muy;
    float cov  = sxy * inv9 - mux * muy;
    float ssim = ((2.f * mux * muy + CC1) * (2.f * cov + CC2)) /
                 ((mux * mux + muy * muy + CC1) * (sigx + sigy + CC2));
    return fminf(fmaxf((1.f - ssim) * 0.5f, 0.f), 1.f);
}

// shared SSIM phase (phase C) for one staged tile
__device__ __forceinline__ float ssim_phase(const float* Xl, const float* Xr,
                                            const float* El, const float* Er,
                                            int col, int rg, int G, int r0,
                                            int H, int W, int APR, float coefS) {
    float acc = 0.f;
    if (col >= 1 && col <= W - 2) {
        if (G == 1) {
            float a0[10], a1[10], a2[10];
            hsum10(Xl, El, Xr, Er, col, a0);
            hsum10(Xl, El, Xr, Er, W + col, a1);
            for (int r = 1; r <= APR; r++) {
                hsum10(Xl, El, Xr, Er, (r + 1) * W + col, a2);
                int gj = r0 + r - 1;
                if (gj >= 1 && gj <= H - 2) {
                    float v = ssim_val(a0[0] + a1[0] + a2[0], a0[1] + a1[1] + a2[1],
                                       a0[2] + a1[2] + a2[2], a0[3] + a1[3] + a2[3],
                                       a0[4] + a1[4] + a2[4]);
                    v += ssim_val(a0[5] + a1[5] + a2[5], a0[6] + a1[6] + a2[6],
                                  a0[7] + a1[7] + a2[7], a0[8] + a1[8] + a2[8],
                                  a0[9] + a1[9] + a2[9]);
                    acc += coefS * v;
                }
                #pragma unroll
                for (int k = 0; k < 10; k++) { a0[k] = a1[k]; a1[k] = a2[k]; }
            }
        } else {
            for (int r = 1 + rg; r <= APR; r += G) {
                int gj = r0 + r - 1;
                if (gj >= 1 && gj <= H - 2) {
                    float a0[10], a1[10], a2[10];
                    hsum10(Xl, El, Xr, Er, (r - 1) * W + col, a0);
                    hsum10(Xl, El, Xr, Er, r * W + col, a1);
                    hsum10(Xl, El, Xr, Er, (r + 1) * W + col, a2);
                    float v = ssim_val(a0[0] + a1[0] + a2[0], a0[1] + a1[1] + a2[1],
                                       a0[2] + a1[2] + a2[2], a0[3] + a1[3] + a2[3],
                                       a0[4] + a1[4] + a2[4]);
                    v += ssim_val(a0[5] + a1[5] + a2[5], a0[6] + a1[6] + a2[6],
                                  a0[7] + a1[7] + a2[7], a0[8] + a1[8] + a2[8],
                                  a0[9] + a1[9] + a2[9]);
                    acc += coefS * v;
                }
            }
        }
    }
    return acc;
}

// ---- ap2_kernel: AP for channels 1 and 2 (blockIdx.z + 1). 4 smem planes.
// disp read directly from global (coalesced, once per pixel).
__global__ __launch_bounds__(NT, 2)
void ap2_kernel(const float* __restrict__ lp, const float* __restrict__ rp,
                const float* __restrict__ disp,
                int H, int W, int lw, int APR,
                float coefS, float coefL) {
    extern __shared__ float sh[];
    int rows = APR + 2;
    int stride = rows * W;
    float* Xl = sh;
    float* Xr = Xl + stride;
    float* El = Xr + stride;
    float* Er = El + stride;

    int tid = threadIdx.x;
    int col = tid & (W - 1);
    int rg = tid >> lw;
    int G = NT >> lw;
    int b = blockIdx.y;
    int c = blockIdx.z + 1;
    int r0 = blockIdx.x * APR;
    long hw = (long)H * W;
    const float* dlg = disp + (long)b * 2 * hw;
    const float* drg = dlg + hw;
    const float* Lg = lp + (long)(b * 3 + c) * hw;
    const float* Rg = rp + (long)(b * 3 + c) * hw;
    float Wm1 = (float)(W - 1);

    // phase A: stage this channel's image planes
    for (int r = rg; r < rows; r += G) {
        int gj = r0 - 1 + r;
        bool in = (gj >= 0 && gj < H);
        long o = (long)gj * W + col;
        int so = r * W + col;
        Xl[so] = in ? Lg[o] : 0.f;
        Xr[so] = in ? Rg[o] : 0.f;
    }
    __syncthreads();

    float accAP = 0.f;

    // phase B: warp from shared (disp straight from global) + L1
    for (int r = rg; r < rows; r += G) {
        int gj = r0 - 1 + r;
        int so = r * W + col;
        float el = 0.f, er = 0.f;
        if (gj >= 0 && gj < H) {
            long o = (long)gj * W + col;
            float dlv = __ldg(dlg + o), drv = __ldg(drg + o);
            el = sample_sh(Xr + r * W, (float)col - dlv * Wm1, W);
            er = sample_sh(Xl + r * W, (float)col + drv * Wm1, W);
            if (r >= 1 && r <= APR)
                accAP += coefL * (fabsf(Xl[so] - el) + fabsf(Xr[so] - er));
        }
        El[so] = el;
        Er[so] = er;
    }
    __syncthreads();

    // phase C: separable SSIM
    accAP += ssim_phase(Xl, Xr, El, Er, col, rg, G, r0, H, W, APR, coefS);

    float s0 = blockReduce(accAP);
    if (tid == 0) atomicAdd(&g_acc[0], (double)s0);
}

// ---- apd_kernel: channel 0 AP + LR + DS. 6 smem planes.
__global__ __launch_bounds__(NT, 2)
void apd_kernel(const float* __restrict__ lp, const float* __restrict__ rp,
                const float* __restrict__ disp,
                int H, int W, int lw, int APR,
                float coefS, float coefL, float coefLR, float coefDS) {
    extern __shared__ float sh[];
    int rows = APR + 2;
    int stride = rows * W;
    float* Dl = sh;
    float* Dr = Dl + stride;
    float* Xl = Dr + stride;
    float* Xr = Xl + stride;
    float* El = Xr + stride;
    float* Er = El + stride;

    int tid = threadIdx.x;
    int col = tid & (W - 1);
    int rg = tid >> lw;
    int G = NT >> lw;
    int b = blockIdx.y;
    int r0 = blockIdx.x * APR;
    long hw = (long)H * W;
    const float* dlg = disp + (long)b * 2 * hw;
    const float* drg = dlg + hw;
    const float* Lg = lp + (long)b * 3 * hw;
    const float* Rg = rp + (long)b * 3 * hw;
    float Wm1 = (float)(W - 1);

    // phase A: stage disp + channel-0 planes
    for (int r = rg; r < rows; r += G) {
        int gj = r0 - 1 + r;
        bool in = (gj >= 0 && gj < H);
        long o = (long)gj * W + col;
        int so = r * W + col;
        Dl[so] = in ? dlg[o] : 0.f;
        Dr[so] = in ? drg[o] : 0.f;
        Xl[so] = in ? Lg[o] : 0.f;
        Xr[so] = in ? Rg[o] : 0.f;
    }
    __syncthreads();

    float accAP = 0.f;

    // phase B: warp estimates from shared + L1
    for (int r = rg; r < rows; r += G) {
        int gj = r0 - 1 + r;
        int so = r * W + col;
        float el = 0.f, er = 0.f;
        if (gj >= 0 && gj < H) {
            float dlv = Dl[so], drv = Dr[so];
            el = sample_sh(Xr + r * W, (float)col - dlv * Wm1, W);
            er = sample_sh(Xl + r * W, (float)col + drv * Wm1, W);
            if (r >= 1 && r <= APR)
                accAP += coefL * (fabsf(Xl[so] - el) + fabsf(Xr[so] - er));
        }
        El[so] = el;
        Er[so] = er;
    }
    __syncthreads();

    // phase C: separable SSIM
    accAP += ssim_phase(Xl, Xr, El, Er, col, rg, G, r0, H, W, APR, coefS);

    float s0 = blockReduce(accAP);
    if (tid == 0) atomicAdd(&g_acc[0], (double)s0);

    // phase D: LR + DS (ch1/2 gradients via __ldg)
    const float* L1g = Lg + hw;
    const float* L2g = Lg + 2 * hw;
    const float* R1g = Rg + hw;
    const float* R2g = Rg + 2 * hw;
    float accLR = 0.f, accDS = 0.f;
    const float third = 1.f / 3.f;
    for (int r = 1 + rg; r <= APR; r += G) {
        int gj = r0 + r - 1;
        if (gj >= H) continue;
        int so = r * W + col;
        long o = (long)gj * W + col;
        float dlv = Dl[so], drv = Dr[so];
        float r2l = sample_sh(Dr + r * W, (float)col - dlv * Wm1, W);
        float l2r = sample_sh(Dl + r * W, (float)col + drv * Wm1, W);
        accLR += fabsf(dlv - r2l) + fabsf(drv - l2r);

        if (col < W - 1) {
            float aL = fabsf(Xl[so] - Xl[so + 1])
                     + fabsf(__ldg(L1g + o) - __ldg(L1g + o + 1))
                     + fabsf(__ldg(L2g + o) - __ldg(L2g + o + 1));
            float aR = fabsf(Xr[so] - Xr[so + 1])
                     + fabsf(__ldg(R1g + o) - __ldg(R1g + o + 1))
                     + fabsf(__ldg(R2g + o) - __ldg(R2g + o + 1));
            accDS += fabsf(dlv - Dl[so + 1]) * __expf(-aL * third)
                   + fabsf(drv - Dr[so + 1]) * __expf(-aR * third);
        }
        if (gj < H - 1) {
            float aL = fabsf(Xl[so] - Xl[so + W])
                     + fabsf(__ldg(L1g + o) - __ldg(L1g + o + W))
                     + fabsf(__ldg(L2g + o) - __ldg(L2g + o + W));
            float aR = fabsf(Xr[so] - Xr[so + W])
                     + fabsf(__ldg(R1g + o) - __ldg(R1g + o + W))
                     + fabsf(__ldg(R2g + o) - __ldg(R2g + o + W));
            accDS += fabsf(dlv - Dl[so + W]) * __expf(-aL * third)
                   + fabsf(drv - Dr[so + W]) * __expf(-aR * third);
        }
    }
    __syncthreads();
    float2 s12 = blockReduce2(accLR, accDS);
    if (tid == 0) {
        atomicAdd(&g_acc[1], (double)(coefLR * s12.x));
        atomicAdd(&g_acc[2], (double)(coefDS * s12.y));
    }
}

__global__ void finalize_kernel(float* __restrict__ out) {
    float AP = (float)g_acc[0];
    float LR = (float)g_acc[1];
    float DS = (float)g_acc[2];
    out[0] = AP + LR + DS;
    out[1] = AP;
    out[2] = LR;
    out[3] = DS;
}

// -------------------- host --------------------
extern "C" void kernel_launch(void* const* d_in, const int* in_sizes, int n_in,
                              void* d_out, int out_size) {
    const float* disp[4];
    for (int i = 0; i < 4; i++) disp[i] = (const float*)d_in[i];
    const float* left = (const float*)d_in[4];
    const float* right = (const float*)d_in[5];

    float *pl, *pr;
    cudaGetSymbolAddress((void**)&pl, g_pyr_l);
    cudaGetSymbolAddress((void**)&pr, g_pyr_r);

    const int H = 256, W = 512;
    const int TB = 256;

    cudaFuncSetAttribute(ap2_kernel, cudaFuncAttributeMaxDynamicSharedMemorySize, 118 * 1024);
    cudaFuncSetAttribute(apd_kernel, cudaFuncAttributeMaxDynamicSharedMemorySize, 118 * 1024);

    zero_acc_kernel<<<1, 32>>>();

    const float* lp[4];
    const float* rp[4];
    lp[0] = left; rp[0] = right;
    float* lbuf[4] = {nullptr, pl + OFF_L1, pl + OFF_L2, pl + OFF_L3};
    float* rbuf[4] = {nullptr, pr + OFF_L1, pr + OFF_L2, pr + OFF_L3};

    for (int i = 1; i < 4; i++) {
        int hin = H >> (i - 1), win = W >> (i - 1);
        int ho = H >> i, wo = W >> i;
        int tot = 2 * BATCH * 3 * ho * wo;
        int grid = (tot + TB - 1) / TB;
        resize_kernel<<<grid, TB>>>(lp[i - 1], rp[i - 1], lbuf[i], rbuf[i], hin, win, ho, wo);
        lp[i] = lbuf[i];
        rp[i] = rbuf[i];
    }

    const int APR2v[4] = {12, 26, 32, 32};   // ap2 (4 planes)
    const int APRDv[4] = {7, 16, 32, 32};    // apd (6 planes)
    const int LWv[4] = {9, 8, 7, 6};

    for (int i = 0; i < 4; i++) {
        int h = H >> i, w = W >> i;
        int totI = BATCH * 3 * h * w;
        int totD = BATCH * h * w;

        float coefS = (A_AP * A_AP) / ((float)BATCH * 3.f * (float)(h - 2) * (float)(w - 2));
        float coefL = (A_AP * (1.f - A_AP)) / (float)totI;
        float coefLR = 1.0f / (float)totD;
        float coefDS = A_DS / ((float)totD * (float)(1 << i));

        {
            int APR = APR2v[i];
            int strips = (h + APR - 1) / APR;
            size_t smem = (size_t)4 * (APR + 2) * w * sizeof(float);
            dim3 grd(strips, BATCH, 2);
            ap2_kernel<<<grd, NT, smem>>>(lp[i], rp[i], disp[i], h, w, LWv[i], APR,
                                          coefS, coefL);
        }
        {
            int APR = APRDv[i];
            int strips = (h + APR - 1) / APR;
            size_t smem = (size_t)6 * (APR + 2) * w * sizeof(float);
            dim3 grd(strips, BATCH);
            apd_kernel<<<grd, NT, smem>>>(lp[i], rp[i], disp[i], h, w, LWv[i], APR,
                                          coefS, coefL, coefLR, coefDS);
        }
    }

    finalize_kernel<<<1, 1>>>((float*)d_out);
}

// round 13
// speedup vs baseline: 1.0101x; 1.0101x over previous
#include <cuda_runtime.h>
#include <math.h>

#define BATCH 32
#define A_AP 0.85f
#define A_DS 0.1f
#define CC1 (0.01f * 0.01f)
#define CC2 (0.03f * 0.03f)
#define NT 512

// ---- static device scratch (no allocs allowed) ----
#define OFF_L1 0
#define OFF_L2 3145728
#define OFF_L3 3932160
#define PYR_TOT 4128768
__device__ float g_pyr_l[PYR_TOT];
__device__ float g_pyr_r[PYR_TOT];
// accumulators: AP, LR, DS
__device__ double g_acc[3];

struct LevelParams {
    const float* lp;
    const float* rp;
    const float* disp;
    int H, W, lw, APR, stripStart;
    float coefS, coefL, coefLR, coefDS;
};
struct AllParams {
    LevelParams lv[4];
};

// -------------------- helpers --------------------
__device__ __forceinline__ float blockReduce(float v) {
    __shared__ float sh[32];
    int tid = threadIdx.x;
    int lane = tid & 31;
    int wid = tid >> 5;
    #pragma unroll
    for (int o = 16; o; o >>= 1) v += __shfl_down_sync(0xffffffffu, v, o);
    if (lane == 0) sh[wid] = v;
    __syncthreads();
    int nw = blockDim.x >> 5;
    v = (tid < nw) ? sh[tid] : 0.0f;
    if (wid == 0) {
        #pragma unroll
        for (int o = 16; o; o >>= 1) v += __shfl_down_sync(0xffffffffu, v, o);
    }
    return v;
}

__device__ __forceinline__ float2 blockReduce2(float a, float b) {
    __shared__ float sha[32], shb[32];
    int tid = threadIdx.x;
    int lane = tid & 31;
    int wid = tid >> 5;
    #pragma unroll
    for (int o = 16; o; o >>= 1) {
        a += __shfl_down_sync(0xffffffffu, a, o);
        b += __shfl_down_sync(0xffffffffu, b, o);
    }
    if (lane == 0) { sha[wid] = a; shb[wid] = b; }
    __syncthreads();
    int nw = blockDim.x >> 5;
    a = (tid < nw) ? sha[tid] : 0.0f;
    b = (tid < nw) ? shb[tid] : 0.0f;
    if (wid == 0) {
        #pragma unroll
        for (int o = 16; o; o >>= 1) {
            a += __shfl_down_sync(0xffffffffu, a, o);
            b += __shfl_down_sync(0xffffffffu, b, o);
        }
    }
    return make_float2(a, b);
}

__global__ void zero_acc_kernel() {
    if (threadIdx.x < 3) g_acc[threadIdx.x] = 0.0;
}

// bilinear align_corners resize, both sides in one launch
__global__ void resize_kernel(const float* __restrict__ inL, const float* __restrict__ inR,
                              float* __restrict__ outL, float* __restrict__ outR,
                              int Hin, int Win, int Hout, int Wout) {
    int idx = blockIdx.x * blockDim.x + threadIdx.x;
    int total = 2 * BATCH * 3 * Hout * Wout;
    if (idx >= total) return;
    int i = idx % Wout; int t = idx / Wout;
    int j = t % Hout;   t /= Hout;
    int c = t % 3;      int b2 = t / 3;
    int side = (b2 >= BATCH);
    int b = b2 - side * BATCH;
    const float* in = side ? inR : inL;
    float* out = side ? outR : outL;

    float sy = (float)(Hin - 1) / (float)(Hout - 1);
    float sx = (float)(Win - 1) / (float)(Wout - 1);
    float y = j * sy, x = i * sx;
    int y0 = (int)floorf(y);
    int y1 = min(y0 + 1, Hin - 1);
    int x0 = (int)floorf(x);
    int x1 = min(x0 + 1, Win - 1);
    float wy = y - (float)y0;
    float wx = x - (float)x0;
    const float* p = in + ((long)(b * 3 + c) * Hin) * Win;
    float tl = p[y0 * Win + x0], tr = p[y0 * Win + x1];
    float bl = p[y1 * Win + x0], br = p[y1 * Win + x1];
    float top = tl * (1.f - wy) + bl * wy;
    float bot = tr * (1.f - wy) + br * wy;
    out[((long)(b * 3 + c) * Hout + j) * Wout + i] = top * (1.f - wx) + bot * wx;
}

// 1-D bilinear gather from a shared row, zero padding outside [0,W-1]
__device__ __forceinline__ float sample_sh(const float* __restrict__ row, float x, int W) {
    float x0f = floorf(x);
    int x0 = (int)x0f;
    float w1 = x - x0f;
    float v = 0.f;
    if (x0 >= 0 && x0 < W) v += row[x0] * (1.f - w1);
    int x1 = x0 + 1;
    if (x1 >= 0 && x1 < W) v += row[x1] * w1;
    return v;
}

// horizontal 3-sums for both stereo sides at shared index 'base'
__device__ __forceinline__ void hsum10(const float* __restrict__ Xl, const float* __restrict__ El,
                                       const float* __restrict__ Xr, const float* __restrict__ Er,
                                       int base, float* o) {
    float x0 = Xl[base - 1], x1 = Xl[base], x2 = Xl[base + 1];
    float e0 = El[base - 1], e1 = El[base], e2 = El[base + 1];
    o[0] = x0 + x1 + x2;
    o[1] = e0 + e1 + e2;
    o[2] = x0 * x0 + x1 * x1 + x2 * x2;
    o[3] = e0 * e0 + e1 * e1 + e2 * e2;
    o[4] = x0 * e0 + x1 * e1 + x2 * e2;
    float u0 = Xr[base - 1], u1 = Xr[base], u2 = Xr[base + 1];
    float v0 = Er[base - 1], v1 = Er[base], v2 = Er[base + 1];
    o[5] = u0 + u1 + u2;
    o[6] = v0 + v1 + v2;
    o[7] = u0 * u0 + u1 * u1 + u2 * u2;
    o[8] = v0 * v0 + v1 * v1 + v2 * v2;
    o[9] = u0 * v0 + u1 * v1 + u2 * v2;
}

__device__ __forceinline__ float ssim_val(float sx, float sy, float sxx, float syy, float sxy) {
    const float inv9 = 1.f / 9.f;
    float mux = sx * inv9, muy = sy * inv9;
    float sigx = sxx * inv9 - mux * mux;
    float sigy = syy * inv9 - muy * muy;
    float cov  = sxy * inv9 - mux * muy;
    float ssim = ((2.f * mux * muy + CC1) * (2.f * cov + CC2)) /
                 ((mux * mux + muy * muy + CC1) * (sigx + sigy + CC2));
    return fminf(fmaxf((1.f - ssim) * 0.5f, 0.f), 1.f);
}

// ---- mega-merged fused kernel: all levels, channel-split, AP + LR + DS ----
// grid: (total strips over levels, BATCH, 3). smem sized for level 0.
__global__ __launch_bounds__(NT, 2)
void ap_kernel(AllParams P) {
    // find level from linear strip index
    int sx = blockIdx.x;
    int li;
    if (sx < P.lv[1].stripStart) li = 0;
    else if (sx < P.lv[2].stripStart) li = 1;
    else if (sx < P.lv[3].stripStart) li = 2;
    else li = 3;
    const LevelParams& L = P.lv[li];

    int H = L.H, W = L.W, lw = L.lw, APR = L.APR;
    extern __shared__ float sh[];
    int rows = APR + 2;
    int stride = rows * W;
    float* Dl = sh;
    float* Dr = Dl + stride;
    float* Xl = Dr + stride;
    float* Xr = Xl + stride;
    float* El = Xr + stride;
    float* Er = El + stride;

    int tid = threadIdx.x;
    int col = tid & (W - 1);
    int rg = tid >> lw;
    int G = NT >> lw;
    int b = blockIdx.y;
    int c = blockIdx.z;
    int r0 = (sx - L.stripStart) * APR;
    long hw = (long)H * W;
    const float* dlg = L.disp + (long)b * 2 * hw;
    const float* drg = dlg + hw;
    const float* Lg = L.lp + (long)(b * 3 + c) * hw;
    const float* Rg = L.rp + (long)(b * 3 + c) * hw;
    float Wm1 = (float)(W - 1);

    // ---- phase A: stage this channel's planes (+disp only for c==0) ----
    for (int r = rg; r < rows; r += G) {
        int gj = r0 - 1 + r;
        bool in = (gj >= 0 && gj < H);
        long o = (long)gj * W + col;
        int so = r * W + col;
        if (c == 0) {
            Dl[so] = in ? dlg[o] : 0.f;
            Dr[so] = in ? drg[o] : 0.f;
        }
        Xl[so] = in ? Lg[o] : 0.f;
        Xr[so] = in ? Rg[o] : 0.f;
    }
    __syncthreads();

    float accAP = 0.f;

    // ---- phase B: warp estimates from shared + L1 term ----
    for (int r = rg; r < rows; r += G) {
        int gj = r0 - 1 + r;
        int so = r * W + col;
        float el = 0.f, er = 0.f;
        if (gj >= 0 && gj < H) {
            long o = (long)gj * W + col;
            float dlv, drv;
            if (c == 0) { dlv = Dl[so]; drv = Dr[so]; }
            else        { dlv = __ldg(dlg + o); drv = __ldg(drg + o); }
            el = sample_sh(Xr + r * W, (float)col - dlv * Wm1, W);
            er = sample_sh(Xl + r * W, (float)col + drv * Wm1, W);
            if (r >= 1 && r <= APR)
                accAP += L.coefL * (fabsf(Xl[so] - el) + fabsf(Xr[so] - er));
        }
        El[so] = el;
        Er[so] = er;
    }
    __syncthreads();

    // ---- phase C: separable SSIM ----
    if (col >= 1 && col <= W - 2) {
        if (G == 1) {
            float a0[10], a1[10], a2[10];
            hsum10(Xl, El, Xr, Er, col, a0);
            hsum10(Xl, El, Xr, Er, W + col, a1);
            for (int r = 1; r <= APR; r++) {
                hsum10(Xl, El, Xr, Er, (r + 1) * W + col, a2);
                int gj = r0 + r - 1;
                if (gj >= 1 && gj <= H - 2) {
                    float v = ssim_val(a0[0] + a1[0] + a2[0], a0[1] + a1[1] + a2[1],
                                       a0[2] + a1[2] + a2[2], a0[3] + a1[3] + a2[3],
                                       a0[4] + a1[4] + a2[4]);
                    v += ssim_val(a0[5] + a1[5] + a2[5], a0[6] + a1[6] + a2[6],
                                  a0[7] + a1[7] + a2[7], a0[8] + a1[8] + a2[8],
                                  a0[9] + a1[9] + a2[9]);
                    accAP += L.coefS * v;
                }
                #pragma unroll
                for (int k = 0; k < 10; k++) { a0[k] = a1[k]; a1[k] = a2[k]; }
            }
        } else {
            for (int r = 1 + rg; r <= APR; r += G) {
                int gj = r0 + r - 1;
                if (gj >= 1 && gj <= H - 2) {
                    float a0[10], a1[10], a2[10];
                    hsum10(Xl, El, Xr, Er, (r - 1) * W + col, a0);
                    hsum10(Xl, El, Xr, Er, r * W + col, a1);
                    hsum10(Xl, El, Xr, Er, (r + 1) * W + col, a2);
                    float v = ssim_val(a0[0] + a1[0] + a2[0], a0[1] + a1[1] + a2[1],
                                       a0[2] + a1[2] + a2[2], a0[3] + a1[3] + a2[3],
                                       a0[4] + a1[4] + a2[4]);
                    v += ssim_val(a0[5] + a1[5] + a2[5], a0[6] + a1[6] + a2[6],
                                  a0[7] + a1[7] + a2[7], a0[8] + a1[8] + a2[8],
                                  a0[9] + a1[9] + a2[9]);
                    accAP += L.coefS * v;
                }
            }
        }
    }

    float s0 = blockReduce(accAP);
    if (tid == 0) atomicAdd(&g_acc[0], (double)s0);

    // ---- phase D (c==0 only): LR consistency + edge-aware smoothness ----
    if (c == 0) {
        const float* L1g = Lg + hw;
        const float* L2g = Lg + 2 * hw;
        const float* R1g = Rg + hw;
        const float* R2g = Rg + 2 * hw;
        float accLR = 0.f, accDS = 0.f;
        const float third = 1.f / 3.f;
        for (int r = 1 + rg; r <= APR; r += G) {
            int gj = r0 + r - 1;
            if (gj >= H) continue;
            int so = r * W + col;
            long o = (long)gj * W + col;
            float dlv = Dl[so], drv = Dr[so];
            float r2l = sample_sh(Dr + r * W, (float)col - dlv * Wm1, W);
            float l2r = sample_sh(Dl + r * W, (float)col + drv * Wm1, W);
            accLR += fabsf(dlv - r2l) + fabsf(drv - l2r);

            if (col < W - 1) {
                float aL = fabsf(Xl[so] - Xl[so + 1])
                         + fabsf(__ldg(L1g + o) - __ldg(L1g + o + 1))
                         + fabsf(__ldg(L2g + o) - __ldg(L2g + o + 1));
                float aR = fabsf(Xr[so] - Xr[so + 1])
                         + fabsf(__ldg(R1g + o) - __ldg(R1g + o + 1))
                         + fabsf(__ldg(R2g + o) - __ldg(R2g + o + 1));
                accDS += fabsf(dlv - Dl[so + 1]) * __expf(-aL * third)
                       + fabsf(drv - Dr[so + 1]) * __expf(-aR * third);
            }
            if (gj < H - 1) {
                float aL = fabsf(Xl[so] - Xl[so + W])
                         + fabsf(__ldg(L1g + o) - __ldg(L1g + o + W))
                         + fabsf(__ldg(L2g + o) - __ldg(L2g + o + W));
                float aR = fabsf(Xr[so] - Xr[so + W])
                         + fabsf(__ldg(R1g + o) - __ldg(R1g + o + W))
                         + fabsf(__ldg(R2g + o) - __ldg(R2g + o + W));
                accDS += fabsf(dlv - Dl[so + W]) * __expf(-aL * third)
                       + fabsf(drv - Dr[so + W]) * __expf(-aR * third);
            }
        }
        __syncthreads();
        float2 s12 = blockReduce2(accLR, accDS);
        if (tid == 0) {
            atomicAdd(&g_acc[1], (double)(L.coefLR * s12.x));
            atomicAdd(&g_acc[2], (double)(L.coefDS * s12.y));
        }
    }
}

__global__ void finalize_kernel(float* __restrict__ out) {
    float AP = (float)g_acc[0];
    float LR = (float)g_acc[1];
    float DS = (float)g_acc[2];
    out[0] = AP + LR + DS;
    out[1] = AP;
    out[2] = LR;
    out[3] = DS;
}

// -------------------- host --------------------
extern "C" void kernel_launch(void* const* d_in, const int* in_sizes, int n_in,
                              void* d_out, int out_size) {
    const float* disp[4];
    for (int i = 0; i < 4; i++) disp[i] = (const float*)d_in[i];
    const float* left = (const float*)d_in[4];
    const float* right = (const float*)d_in[5];

    float *pl, *pr;
    cudaGetSymbolAddress((void**)&pl, g_pyr_l);
    cudaGetSymbolAddress((void**)&pr, g_pyr_r);

    const int H = 256, W = 512;
    const int TB = 256;

    cudaFuncSetAttribute(ap_kernel, cudaFuncAttributeMaxDynamicSharedMemorySize, 100 * 1024);

    zero_acc_kernel<<<1, 32>>>();

    const float* lp[4];
    const float* rp[4];
    lp[0] = left; rp[0] = right;
    float* lbuf[4] = {nullptr, pl + OFF_L1, pl + OFF_L2, pl + OFF_L3};
    float* rbuf[4] = {nullptr, pr + OFF_L1, pr + OFF_L2, pr + OFF_L3};

    for (int i = 1; i < 4; i++) {
        int hin = H >> (i - 1), win = W >> (i - 1);
        int ho = H >> i, wo = W >> i;
        int tot = 2 * BATCH * 3 * ho * wo;
        int grid = (tot + TB - 1) / TB;
        resize_kernel<<<grid, TB>>>(lp[i - 1], rp[i - 1], lbuf[i], rbuf[i], hin, win, ho, wo);
        lp[i] = lbuf[i];
        rp[i] = rbuf[i];
    }

    const int APRv[4] = {6, 8, 16, 32};
    const int LWv[4] = {9, 8, 7, 6};

    AllParams P;
    int stripAcc = 0;
    for (int i = 0; i < 4; i++) {
        int h = H >> i, w = W >> i;
        int totI = BATCH * 3 * h * w;
        int totD = BATCH * h * w;
        LevelParams& L = P.lv[i];
        L.lp = lp[i];
        L.rp = rp[i];
        L.disp = disp[i];
        L.H = h; L.W = w; L.lw = LWv[i]; L.APR = APRv[i];
        L.stripStart = stripAcc;
        L.coefS = (A_AP * A_AP) / ((float)BATCH * 3.f * (float)(h - 2) * (float)(w - 2));
        L.coefL = (A_AP * (1.f - A_AP)) / (float)totI;
        L.coefLR = 1.0f / (float)totD;
        L.coefDS = A_DS / ((float)totD * (float)(1 << i));
        stripAcc += (h + APRv[i] - 1) / APRv[i];
    }

    // smem sized for level 0 (largest): 6 planes * (APR0+2) rows * W0
    size_t smem = (size_t)6 * (APRv[0] + 2) * W * sizeof(float);
    dim3 grd(stripAcc, BATCH, 3);
    ap_kernel<<<grd, NT, smem>>>(P);

    finalize_kernel<<<1, 1>>>((float*)d_out);
}

// round 14
// speedup vs baseline: 1.2714x; 1.2587x over previous
#include <cuda_runtime.h>
#include <math.h>

#define BATCH 32
#define A_AP 0.85f
#define A_DS 0.1f
#define CC1 (0.01f * 0.01f)
#define CC2 (0.03f * 0.03f)
#define NT 512

// ---- static device scratch (no allocs allowed) ----
#define OFF_L1 0
#define OFF_L2 3145728
#define OFF_L3 3932160
#define PYR_TOT 4128768
__device__ float g_pyr_l[PYR_TOT];
__device__ float g_pyr_r[PYR_TOT];
// accumulators: AP, LR, DS
__device__ double g_acc[3];

struct LevelParams {
    const float* lp;
    const float* rp;
    const float* disp;
    int H, W, lw, APR, stripStart;
    float coefS, coefL, coefLR, coefDS;
};
struct AllParams {
    LevelParams lv[4];
};

// -------------------- helpers --------------------
__device__ __forceinline__ float blockReduce(float v) {
    __shared__ float sh[32];
    int tid = threadIdx.x;
    int lane = tid & 31;
    int wid = tid >> 5;
    #pragma unroll
    for (int o = 16; o; o >>= 1) v += __shfl_down_sync(0xffffffffu, v, o);
    if (lane == 0) sh[wid] = v;
    __syncthreads();
    int nw = blockDim.x >> 5;
    v = (tid < nw) ? sh[tid] : 0.0f;
    if (wid == 0) {
        #pragma unroll
        for (int o = 16; o; o >>= 1) v += __shfl_down_sync(0xffffffffu, v, o);
    }
    return v;
}

__device__ __forceinline__ float2 blockReduce2(float a, float b) {
    __shared__ float sha[32], shb[32];
    int tid = threadIdx.x;
    int lane = tid & 31;
    int wid = tid >> 5;
    #pragma unroll
    for (int o = 16; o; o >>= 1) {
        a += __shfl_down_sync(0xffffffffu, a, o);
        b += __shfl_down_sync(0xffffffffu, b, o);
    }
    if (lane == 0) { sha[wid] = a; shb[wid] = b; }
    __syncthreads();
    int nw = blockDim.x >> 5;
    a = (tid < nw) ? sha[tid] : 0.0f;
    b = (tid < nw) ? shb[tid] : 0.0f;
    if (wid == 0) {
        #pragma unroll
        for (int o = 16; o; o >>= 1) {
            a += __shfl_down_sync(0xffffffffu, a, o);
            b += __shfl_down_sync(0xffffffffu, b, o);
        }
    }
    return make_float2(a, b);
}

__global__ void zero_acc_kernel() {
    if (threadIdx.x < 3) g_acc[threadIdx.x] = 0.0;
}

// bilinear align_corners resize, both sides in one launch
__global__ void resize_kernel(const float* __restrict__ inL, const float* __restrict__ inR,
                              float* __restrict__ outL, float* __restrict__ outR,
                              int Hin, int Win, int Hout, int Wout) {
    int idx = blockIdx.x * blockDim.x + threadIdx.x;
    int total = 2 * BATCH * 3 * Hout * Wout;
    if (idx >= total) return;
    int i = idx % Wout; int t = idx / Wout;
    int j = t % Hout;   t /= Hout;
    int c = t % 3;      int b2 = t / 3;
    int side = (b2 >= BATCH);
    int b = b2 - side * BATCH;
    const float* in = side ? inR : inL;
    float* out = side ? outR : outL;

    float sy = (float)(Hin - 1) / (float)(Hout - 1);
    float sx = (float)(Win - 1) / (float)(Wout - 1);
    float y = j * sy, x = i * sx;
    int y0 = (int)floorf(y);
    int y1 = min(y0 + 1, Hin - 1);
    int x0 = (int)floorf(x);
    int x1 = min(x0 + 1, Win - 1);
    float wy = y - (float)y0;
    float wx = x - (float)x0;
    const float* p = in + ((long)(b * 3 + c) * Hin) * Win;
    float tl = p[y0 * Win + x0], tr = p[y0 * Win + x1];
    float bl = p[y1 * Win + x0], br = p[y1 * Win + x1];
    float top = tl * (1.f - wy) + bl * wy;
    float bot = tr * (1.f - wy) + br * wy;
    out[((long)(b * 3 + c) * Hout + j) * Wout + i] = top * (1.f - wx) + bot * wx;
}

// 1-D bilinear gather from a shared row, zero padding outside [0,W-1]
__device__ __forceinline__ float sample_sh(const float* __restrict__ row, float x, int W) {
    float x0f = floorf(x);
    int x0 = (int)x0f;
    float w1 = x - x0f;
    float v = 0.f;
    if (x0 >= 0 && x0 < W) v += row[x0] * (1.f - w1);
    int x1 = x0 + 1;
    if (x1 >= 0 && x1 < W) v += row[x1] * w1;
    return v;
}

// horizontal 3-sums for both stereo sides at shared index 'base'
__device__ __forceinline__ void hsum10(const float* __restrict__ Xl, const float* __restrict__ El,
                                       const float* __restrict__ Xr, const float* __restrict__ Er,
                                       int base, float* o) {
    float x0 = Xl[base - 1], x1 = Xl[base], x2 = Xl[base + 1];
    float e0 = El[base - 1], e1 = El[base], e2 = El[base + 1];
    o[0] = x0 + x1 + x2;
    o[1] = e0 + e1 + e2;
    o[2] = x0 * x0 + x1 * x1 + x2 * x2;
    o[3] = e0 * e0 + e1 * e1 + e2 * e2;
    o[4] = x0 * e0 + x1 * e1 + x2 * e2;
    float u0 = Xr[base - 1], u1 = Xr[base], u2 = Xr[base + 1];
    float v0 = Er[base - 1], v1 = Er[base], v2 = Er[base + 1];
    o[5] = u0 + u1 + u2;
    o[6] = v0 + v1 + v2;
    o[7] = u0 * u0 + u1 * u1 + u2 * u2;
    o[8] = v0 * v0 + v1 * v1 + v2 * v2;
    o[9] = u0 * v0 + u1 * v1 + u2 * v2;
}

__device__ __forceinline__ float ssim_val(float sx, float sy, float sxx, float syy, float sxy) {
    const float inv9 = 1.f / 9.f;
    float mux = sx * inv9, muy = sy * inv9;
    float sigx = sxx * inv9 - mux * mux;
    float sigy = syy * inv9 - muy * muy;
    float cov  = sxy * inv9 - mux * muy;
    float ssim = ((2.f * mux * muy + CC1) * (2.f * cov + CC2)) /
                 ((mux * mux + muy * muy + CC1) * (sigx + sigy + CC2));
    return fminf(fmaxf((1.f - ssim) * 0.5f, 0.f), 1.f);
}

// ---- mega-merged fused kernel: all levels, channel-split, AP + LR + DS ----
// grid: (total strips over levels, BATCH, 3). smem sized for level 0.
// All blocks stage Dl/Dr in shared (phase B reads disp from SMEM — keeping the
// global disp load in the bulk-parallel phase A is what the 302us baseline did).
__global__ __launch_bounds__(NT, 2)
void ap_kernel(AllParams P) {
    int sx = blockIdx.x;
    int li;
    if (sx < P.lv[1].stripStart) li = 0;
    else if (sx < P.lv[2].stripStart) li = 1;
    else if (sx < P.lv[3].stripStart) li = 2;
    else li = 3;
    const LevelParams& L = P.lv[li];

    int H = L.H, W = L.W, lw = L.lw, APR = L.APR;
    extern __shared__ float sh[];
    int rows = APR + 2;
    int stride = rows * W;
    float* Dl = sh;
    float* Dr = Dl + stride;
    float* Xl = Dr + stride;
    float* Xr = Xl + stride;
    float* El = Xr + stride;
    float* Er = El + stride;

    int tid = threadIdx.x;
    int col = tid & (W - 1);
    int rg = tid >> lw;
    int G = NT >> lw;
    int b = blockIdx.y;
    int c = blockIdx.z;
    int r0 = (sx - L.stripStart) * APR;
    long hw = (long)H * W;
    const float* dlg = L.disp + (long)b * 2 * hw;
    const float* drg = dlg + hw;
    const float* Lg = L.lp + (long)(b * 3 + c) * hw;
    const float* Rg = L.rp + (long)(b * 3 + c) * hw;
    float Wm1 = (float)(W - 1);

    // ---- phase A: stage disp + this channel's planes ----
    for (int r = rg; r < rows; r += G) {
        int gj = r0 - 1 + r;
        bool in = (gj >= 0 && gj < H);
        long o = (long)gj * W + col;
        int so = r * W + col;
        Dl[so] = in ? dlg[o] : 0.f;
        Dr[so] = in ? drg[o] : 0.f;
        Xl[so] = in ? Lg[o] : 0.f;
        Xr[so] = in ? Rg[o] : 0.f;
    }
    __syncthreads();

    float accAP = 0.f;

    // ---- phase B: warp estimates from shared + L1 term ----
    for (int r = rg; r < rows; r += G) {
        int gj = r0 - 1 + r;
        int so = r * W + col;
        float el = 0.f, er = 0.f;
        if (gj >= 0 && gj < H) {
            float dlv = Dl[so], drv = Dr[so];
            el = sample_sh(Xr + r * W, (float)col - dlv * Wm1, W);
            er = sample_sh(Xl + r * W, (float)col + drv * Wm1, W);
            if (r >= 1 && r <= APR)
                accAP += L.coefL * (fabsf(Xl[so] - el) + fabsf(Xr[so] - er));
        }
        El[so] = el;
        Er[so] = er;
    }
    __syncthreads();

    // ---- phase C: separable SSIM ----
    if (col >= 1 && col <= W - 2) {
        if (G == 1) {
            float a0[10], a1[10], a2[10];
            hsum10(Xl, El, Xr, Er, col, a0);
            hsum10(Xl, El, Xr, Er, W + col, a1);
            for (int r = 1; r <= APR; r++) {
                hsum10(Xl, El, Xr, Er, (r + 1) * W + col, a2);
                int gj = r0 + r - 1;
                if (gj >= 1 && gj <= H - 2) {
                    float v = ssim_val(a0[0] + a1[0] + a2[0], a0[1] + a1[1] + a2[1],
                                       a0[2] + a1[2] + a2[2], a0[3] + a1[3] + a2[3],
                                       a0[4] + a1[4] + a2[4]);
                    v += ssim_val(a0[5] + a1[5] + a2[5], a0[6] + a1[6] + a2[6],
                                  a0[7] + a1[7] + a2[7], a0[8] + a1[8] + a2[8],
                                  a0[9] + a1[9] + a2[9]);
                    accAP += L.coefS * v;
                }
                #pragma unroll
                for (int k = 0; k < 10; k++) { a0[k] = a1[k]; a1[k] = a2[k]; }
            }
        } else {
            for (int r = 1 + rg; r <= APR; r += G) {
                int gj = r0 + r - 1;
                if (gj >= 1 && gj <= H - 2) {
                    float a0[10], a1[10], a2[10];
                    hsum10(Xl, El, Xr, Er, (r - 1) * W + col, a0);
                    hsum10(Xl, El, Xr, Er, r * W + col, a1);
                    hsum10(Xl, El, Xr, Er, (r + 1) * W + col, a2);
                    float v = ssim_val(a0[0] + a1[0] + a2[0], a0[1] + a1[1] + a2[1],
                                       a0[2] + a1[2] + a2[2], a0[3] + a1[3] + a2[3],
                                       a0[4] + a1[4] + a2[4]);
                    v += ssim_val(a0[5] + a1[5] + a2[5], a0[6] + a1[6] + a2[6],
                                  a0[7] + a1[7] + a2[7], a0[8] + a1[8] + a2[8],
                                  a0[9] + a1[9] + a2[9]);
                    accAP += L.coefS * v;
                }
            }
        }
    }

    float s0 = blockReduce(accAP);
    if (tid == 0) atomicAdd(&g_acc[0], (double)s0);

    // ---- phase D (c==0 only): LR consistency + edge-aware smoothness ----
    if (c == 0) {
        const float* L1g = Lg + hw;
        const float* L2g = Lg + 2 * hw;
        const float* R1g = Rg + hw;
        const float* R2g = Rg + 2 * hw;
        float accLR = 0.f, accDS = 0.f;
        const float third = 1.f / 3.f;
        for (int r = 1 + rg; r <= APR; r += G) {
            int gj = r0 + r - 1;
            if (gj >= H) continue;
            int so = r * W + col;
            long o = (long)gj * W + col;
            float dlv = Dl[so], drv = Dr[so];
            float r2l = sample_sh(Dr + r * W, (float)col - dlv * Wm1, W);
            float l2r = sample_sh(Dl + r * W, (float)col + drv * Wm1, W);
            accLR += fabsf(dlv - r2l) + fabsf(drv - l2r);

            if (col < W - 1) {
                float aL = fabsf(Xl[so] - Xl[so + 1])
                         + fabsf(__ldg(L1g + o) - __ldg(L1g + o + 1))
                         + fabsf(__ldg(L2g + o) - __ldg(L2g + o + 1));
                float aR = fabsf(Xr[so] - Xr[so + 1])
                         + fabsf(__ldg(R1g + o) - __ldg(R1g + o + 1))
                         + fabsf(__ldg(R2g + o) - __ldg(R2g + o + 1));
                accDS += fabsf(dlv - Dl[so + 1]) * __expf(-aL * third)
                       + fabsf(drv - Dr[so + 1]) * __expf(-aR * third);
            }
            if (gj < H - 1) {
                float aL = fabsf(Xl[so] - Xl[so + W])
                         + fabsf(__ldg(L1g + o) - __ldg(L1g + o + W))
                         + fabsf(__ldg(L2g + o) - __ldg(L2g + o + W));
                float aR = fabsf(Xr[so] - Xr[so + W])
                         + fabsf(__ldg(R1g + o) - __ldg(R1g + o + W))
                         + fabsf(__ldg(R2g + o) - __ldg(R2g + o + W));
                accDS += fabsf(dlv - Dl[so + W]) * __expf(-aL * third)
                       + fabsf(drv - Dr[so + W]) * __expf(-aR * third);
            }
        }
        __syncthreads();
        float2 s12 = blockReduce2(accLR, accDS);
        if (tid == 0) {
            atomicAdd(&g_acc[1], (double)(L.coefLR * s12.x));
            atomicAdd(&g_acc[2], (double)(L.coefDS * s12.y));
        }
    }
}

__global__ void finalize_kernel(float* __restrict__ out) {
    float AP = (float)g_acc[0];
    float LR = (float)g_acc[1];
    float DS = (float)g_acc[2];
    out[0] = AP + LR + DS;
    out[1] = AP;
    out[2] = LR;
    out[3] = DS;
}

// -------------------- host --------------------
extern "C" void kernel_launch(void* const* d_in, const int* in_sizes, int n_in,
                              void* d_out, int out_size) {
    const float* disp[4];
    for (int i = 0; i < 4; i++) disp[i] = (const float*)d_in[i];
    const float* left = (const float*)d_in[4];
    const float* right = (const float*)d_in[5];

    float *pl, *pr;
    cudaGetSymbolAddress((void**)&pl, g_pyr_l);
    cudaGetSymbolAddress((void**)&pr, g_pyr_r);

    const int H = 256, W = 512;
    const int TB = 256;

    cudaFuncSetAttribute(ap_kernel, cudaFuncAttributeMaxDynamicSharedMemorySize, 100 * 1024);

    zero_acc_kernel<<<1, 32>>>();

    const float* lp[4];
    const float* rp[4];
    lp[0] = left; rp[0] = right;
    float* lbuf[4] = {nullptr, pl + OFF_L1, pl + OFF_L2, pl + OFF_L3};
    float* rbuf[4] = {nullptr, pr + OFF_L1, pr + OFF_L2, pr + OFF_L3};

    for (int i = 1; i < 4; i++) {
        int hin = H >> (i - 1), win = W >> (i - 1);
        int ho = H >> i, wo = W >> i;
        int tot = 2 * BATCH * 3 * ho * wo;
        int grid = (tot + TB - 1) / TB;
        resize_kernel<<<grid, TB>>>(lp[i - 1], rp[i - 1], lbuf[i], rbuf[i], hin, win, ho, wo);
        lp[i] = lbuf[i];
        rp[i] = rbuf[i];
    }

    const int APRv[4] = {6, 8, 16, 32};
    const int LWv[4] = {9, 8, 7, 6};

    AllParams P;
    int stripAcc = 0;
    for (int i = 0; i < 4; i++) {
        int h = H >> i, w = W >> i;
        int totI = BATCH * 3 * h * w;
        int totD = BATCH * h * w;
        LevelParams& L = P.lv[i];
        L.lp = lp[i];
        L.rp = rp[i];
        L.disp = disp[i];
        L.H = h; L.W = w; L.lw = LWv[i]; L.APR = APRv[i];
        L.stripStart = stripAcc;
        L.coefS = (A_AP * A_AP) / ((float)BATCH * 3.f * (float)(h - 2) * (float)(w - 2));
        L.coefL = (A_AP * (1.f - A_AP)) / (float)totI;
        L.coefLR = 1.0f / (float)totD;
        L.coefDS = A_DS / ((float)totD * (float)(1 << i));
        stripAcc += (h + APRv[i] - 1) / APRv[i];
    }

    // smem sized for level 0 (largest): 6 planes * (APR0+2) rows * W0
    size_t smem = (size_t)6 * (APRv[0] + 2) * W * sizeof(float);
    dim3 grd(stripAcc, BATCH, 3);
    ap_kernel<<<grd, NT, smem>>>(P);

    finalize_kernel<<<1, 1>>>((float*)d_out);
}